// round 1
// baseline (speedup 1.0000x reference)
#include <cuda_runtime.h>
#include <cuda_bf16.h>
#include <math.h>

#define DIM   128
#define NSEG  4096
#define W1S   132            // padded row stride for W1 in smem (16B-aligned, conflict-free LDS.128)
#define MAXN  2000128

// ---------------- scratch (static __device__, no allocation) ----------------
__device__ float g_s[MAXN];       // per-row scores
__device__ float g_m[NSEG];       // per-segment max (finite-sanitized)
__device__ float g_z[NSEG];       // per-segment sum of exp
__device__ int   g_beg[NSEG];
__device__ int   g_end[NSEG];
__device__ int   g_is64;          // batch_idx dtype flag

// ---------------- helpers ----------------
__device__ __forceinline__ int idx_at(const void* p, int i, int is64) {
    if (is64) return (int)((const long long*)p)[i];
    return ((const int*)p)[i];
}

__device__ __forceinline__ float f4c(const float4 v, int i) {
    switch (i) { case 0: return v.x; case 1: return v.y; case 2: return v.z; default: return v.w; }
}

// ---------------- K0: detect batch_idx element width ----------------
// Sorted indices in [0,4096). Probe int64 words at element n/4: for int32 data
// that fuses two mid-array indices (~2048 each) into a huge value -> detected.
// Byte range [2n, 2n+24) is in-bounds for both widths.
__global__ void k0_detect(const void* __restrict__ idx, int n) {
    const long long* p = (const long long*)idx;
    long long j = n / 4;
    int ok = 1;
    for (int t = 0; t < 3; t++) {
        long long v = p[j + t];
        if (v < 0 || v >= NSEG) ok = 0;
    }
    g_is64 = ok;
}

// ---------------- K1: scores s = tanh(x@W1+b1)@W2+b2 ----------------
// Persistent blocks: W1/b1/W2 loaded into smem once per block. Per tile of 32
// rows, 8 warps x 4 rows each; each lane owns 4 output columns (lane*4..+3).
__global__ void k1_scores(const float* __restrict__ x,  const float* __restrict__ W1,
                          const float* __restrict__ b1, const float* __restrict__ W2,
                          const float* __restrict__ b2, int nrows, int ntiles) {
    extern __shared__ float sm[];
    float* W1s = sm;                 // DIM * W1S
    float* b1s = W1s + DIM * W1S;    // DIM
    float* W2s = b1s + DIM;          // DIM
    float* xs  = W2s + DIM;          // 32 * DIM

    const int tid = threadIdx.x;     // 256 threads
    for (int i = tid; i < DIM * DIM; i += 256)
        W1s[(i >> 7) * W1S + (i & 127)] = W1[i];
    if (tid < DIM) { b1s[tid] = b1[tid]; W2s[tid] = W2[tid]; }
    const float b2v = b2[0];
    __syncthreads();

    const int warp = tid >> 5, lane = tid & 31;
    float w2v[4], bini[4];
#pragma unroll
    for (int c = 0; c < 4; c++) { w2v[c] = W2s[lane * 4 + c]; bini[c] = b1s[lane * 4 + c]; }

    for (int tile = blockIdx.x; tile < ntiles; tile += gridDim.x) {
        const long long row0 = (long long)tile * 32;
        __syncthreads();  // protect xs readers from previous iteration
        const float4* xg  = (const float4*)(x + row0 * DIM);
        float4*       xs4 = (float4*)xs;
#pragma unroll
        for (int i = 0; i < 4; i++) {
            int e = tid + i * 256;          // float4 index; row = e/32
            int r = e >> 5;
            float4 v = make_float4(0.f, 0.f, 0.f, 0.f);
            if (row0 + r < nrows) v = xg[e];
            xs4[e] = v;
        }
        __syncthreads();

        float acc[4][4];
#pragma unroll
        for (int r = 0; r < 4; r++)
#pragma unroll
            for (int c = 0; c < 4; c++) acc[r][c] = bini[c];

#pragma unroll 4
        for (int k0 = 0; k0 < DIM; k0 += 4) {
            float4 xv[4];
#pragma unroll
            for (int r = 0; r < 4; r++)
                xv[r] = *(const float4*)&xs[(warp * 4 + r) * DIM + k0];  // broadcast LDS.128
#pragma unroll
            for (int kk = 0; kk < 4; kk++) {
                float4 w = *(const float4*)&W1s[(k0 + kk) * W1S + lane * 4];
#pragma unroll
                for (int r = 0; r < 4; r++) {
                    float xval = f4c(xv[r], kk);
                    acc[r][0] = fmaf(xval, w.x, acc[r][0]);
                    acc[r][1] = fmaf(xval, w.y, acc[r][1]);
                    acc[r][2] = fmaf(xval, w.z, acc[r][2]);
                    acc[r][3] = fmaf(xval, w.w, acc[r][3]);
                }
            }
        }

#pragma unroll
        for (int r = 0; r < 4; r++) {
            float p = 0.f;
#pragma unroll
            for (int c = 0; c < 4; c++) p = fmaf(tanhf(acc[r][c]), w2v[c], p);
#pragma unroll
            for (int o = 16; o > 0; o >>= 1) p += __shfl_xor_sync(0xffffffffu, p, o);
            long long row = row0 + warp * 4 + r;
            if (lane == 0 && row < nrows) g_s[row] = p + b2v;
        }
    }
}

// ---------------- K3: per-segment max + sum(exp) ----------------
__global__ void k3_stats(const void* __restrict__ idx, int n) {
    __shared__ float redm[8];
    __shared__ float redz[8];
    __shared__ int   range[2];
    __shared__ float sm_m;

    const int seg  = blockIdx.x;
    const int is64 = g_is64;
    if (threadIdx.x < 2) {  // lower_bound(seg) and lower_bound(seg+1)
        int target = seg + (int)threadIdx.x;
        int lo = 0, hi = n;
        while (lo < hi) { int mid = (lo + hi) >> 1; if (idx_at(idx, mid, is64) < target) lo = mid + 1; else hi = mid; }
        range[threadIdx.x] = lo;
    }
    __syncthreads();
    const int b = range[0], e = range[1];

    float m = __int_as_float(0xff800000u);  // -inf
    for (int i = b + threadIdx.x; i < e; i += 256) m = fmaxf(m, g_s[i]);
#pragma unroll
    for (int o = 16; o > 0; o >>= 1) m = fmaxf(m, __shfl_xor_sync(0xffffffffu, m, o));
    if ((threadIdx.x & 31) == 0) redm[threadIdx.x >> 5] = m;
    __syncthreads();
    if (threadIdx.x == 0) {
        float mm = redm[0];
#pragma unroll
        for (int w = 1; w < 8; w++) mm = fmaxf(mm, redm[w]);
        if (!(mm > -3.0e38f && mm < 3.0e38f)) mm = 0.0f;  // isfinite -> else 0 (empty seg)
        sm_m = mm;
    }
    __syncthreads();
    const float mfin = sm_m;

    float z = 0.f;
    for (int i = b + threadIdx.x; i < e; i += 256) z += expf(g_s[i] - mfin);
#pragma unroll
    for (int o = 16; o > 0; o >>= 1) z += __shfl_xor_sync(0xffffffffu, z, o);
    if ((threadIdx.x & 31) == 0) redz[threadIdx.x >> 5] = z;
    __syncthreads();
    if (threadIdx.x == 0) {
        float zz = 0.f;
#pragma unroll
        for (int w = 0; w < 8; w++) zz += redz[w];
        g_m[seg] = mfin; g_z[seg] = zz; g_beg[seg] = b; g_end[seg] = e;
    }
}

// ---------------- K4: alpha + weighted segment aggregation ----------------
// One block per segment, 128 threads = one column each. Unroll-4 batches the
// x/s loads (MLP>=8) to cover L2/DRAM latency across the serial row loop.
__global__ void k4_agg(const float* __restrict__ x, float* __restrict__ out,
                       float* __restrict__ alpha, int n) {
    const int seg = blockIdx.x;
    const int b = g_beg[seg], e = g_end[seg];
    const float m    = g_m[seg];
    const float invz = 1.0f / (g_z[seg] + 1e-16f);
    const int c = threadIdx.x;

    float acc = 0.f;
    int i = b;
    for (; i + 4 <= e; i += 4) {
        float s0 = g_s[i], s1 = g_s[i + 1], s2 = g_s[i + 2], s3 = g_s[i + 3];
        float x0 = x[(long long)(i    ) * DIM + c];
        float x1 = x[(long long)(i + 1) * DIM + c];
        float x2 = x[(long long)(i + 2) * DIM + c];
        float x3 = x[(long long)(i + 3) * DIM + c];
        float a0 = expf(s0 - m) * invz, a1 = expf(s1 - m) * invz;
        float a2 = expf(s2 - m) * invz, a3 = expf(s3 - m) * invz;
        acc = fmaf(x0, a0, acc); acc = fmaf(x1, a1, acc);
        acc = fmaf(x2, a2, acc); acc = fmaf(x3, a3, acc);
        if (alpha && c == 0) { alpha[i] = a0; alpha[i + 1] = a1; alpha[i + 2] = a2; alpha[i + 3] = a3; }
    }
    for (; i < e; i++) {
        float a0 = expf(g_s[i] - m) * invz;
        acc = fmaf(x[(long long)i * DIM + c], a0, acc);
        if (alpha && c == 0) alpha[i] = a0;
    }
    if (out) out[seg * DIM + c] = acc;  // empty segments write 0 (d_out is poisoned)
}

// ---------------- launch ----------------
extern "C" void kernel_launch(void* const* d_in, const int* in_sizes, int n_in,
                              void* d_out, int out_size) {
    const float* x   = (const float*)d_in[0];
    const float* W1  = (const float*)d_in[1];
    const float* b1  = (const float*)d_in[2];
    const float* W2  = (const float*)d_in[3];
    const float* b2  = (const float*)d_in[4];
    const void*  idx = d_in[5];
    const int n = in_sizes[0] / DIM;

    // Output layout: reference returns (out[4096,128], alpha[N]); derive from out_size.
    float* out_ptr = nullptr;
    float* alpha_ptr = nullptr;
    if (out_size == NSEG * DIM + n)      { out_ptr = (float*)d_out; alpha_ptr = out_ptr + NSEG * DIM; }
    else if (out_size == n)              { alpha_ptr = (float*)d_out; }
    else                                 { out_ptr = (float*)d_out;
                                           if (out_size > NSEG * DIM) alpha_ptr = out_ptr + NSEG * DIM; }

    const size_t smem = (size_t)(DIM * W1S + DIM + DIM + 32 * DIM) * sizeof(float);
    cudaFuncSetAttribute(k1_scores, cudaFuncAttributeMaxDynamicSharedMemorySize, (int)smem);

    k0_detect<<<1, 1>>>(idx, n);

    const int ntiles = (n + 31) / 32;
    const int grid = ntiles < 296 ? ntiles : 296;   // 2 CTAs/SM x 148 SMs
    k1_scores<<<grid, 256, smem>>>(x, W1, b1, W2, b2, n, ntiles);

    k3_stats<<<NSEG, 256>>>(idx, n);
    k4_agg<<<NSEG, DIM>>>(x, out_ptr, alpha_ptr, n);
}

// round 4
// speedup vs baseline: 2.2659x; 2.2659x over previous
#include <cuda_runtime.h>
#include <cuda_bf16.h>
#include <math.h>
#include <stdint.h>

#define DIM   128
#define NSEG  4096
#define MAXN  2000128

// ---------------- scratch ----------------
__device__ float g_s[MAXN];
__device__ float g_m[NSEG];
__device__ float g_z[NSEG];
__device__ int   g_beg[NSEG];
__device__ int   g_end[NSEG];
__device__ int   g_is64;

__device__ __forceinline__ uint32_t smem_to_u32(const void* p) {
    uint32_t a;
    asm("{ .reg .u64 t; cvta.to.shared.u64 t, %1; cvt.u32.u64 %0, t; }" : "=r"(a) : "l"(p));
    return a;
}
__device__ __forceinline__ uint32_t pack_bf16(float a, float b) {
    __nv_bfloat162 t;
    t.x = __float2bfloat16(a); t.y = __float2bfloat16(b);
    return *reinterpret_cast<uint32_t*>(&t);
}
__device__ __forceinline__ int idx_at(const void* p, int i, int is64) {
    if (is64) return (int)((const long long*)p)[i];
    return ((const int*)p)[i];
}

#define LDSM_X4(a0, a1, a2, a3, addr)                                          \
    asm volatile("ldmatrix.sync.aligned.m8n8.x4.shared.b16 {%0,%1,%2,%3},[%4];"\
        : "=r"(a0), "=r"(a1), "=r"(a2), "=r"(a3) : "r"(addr))

#define MMA_BF16(d, a0, a1, a2, a3, b0, b1)                                    \
    asm volatile("mma.sync.aligned.m16n8k16.row.col.f32.bf16.bf16.f32 "        \
        "{%0,%1,%2,%3},{%4,%5,%6,%7},{%8,%9},{%0,%1,%2,%3};"                   \
        : "+f"((d)[0]), "+f"((d)[1]), "+f"((d)[2]), "+f"((d)[3])               \
        : "r"(a0), "r"(a1), "r"(a2), "r"(a3), "r"(b0), "r"(b1))

// ---------------- K0: detect batch_idx width ----------------
__global__ void k0_detect(const void* __restrict__ idx, int n) {
    const long long* p = (const long long*)idx;
    long long j = n / 4;
    int ok = 1;
    for (int t = 0; t < 3; t++) {
        long long v = p[j + t];
        if (v < 0 || v >= NSEG) ok = 0;
    }
    g_is64 = ok;
}

// ---------------- K1: HMMA bf16x3 GEMM + tanh + dot(W2) ----------------
// smem: A_hi [0,32K), A_lo [32K,64K)  (128 rows x 128 bf16, 256B row stride,
//       16B chunks swizzled: chunk' = chunk ^ (row&7));  part [64K, 64K+4K).
#define SM_AHI  0
#define SM_ALO  32768
#define SM_PART 65536
#define SM_K1_SZ (SM_PART + 128 * 8 * 4)

__global__ void __launch_bounds__(256, 2) k1_scores(
        const float* __restrict__ x,  const float* __restrict__ W1,
        const float* __restrict__ b1, const float* __restrict__ W2,
        const float* __restrict__ b2, int nrows, int ntiles) {
    extern __shared__ char smem[];
    float* part = (float*)(smem + SM_PART);
    const uint32_t smA = smem_to_u32(smem);

    const int tid  = threadIdx.x;       // 256 threads, 8 warps
    const int w    = tid >> 5;
    const int lane = tid & 31;
    const int g    = lane >> 2;         // groupID (row within fragment)
    const int tig  = lane & 3;          // thread-in-group (col pairs)

    // ---- W1^T hi/lo B-fragments, register-resident (warp owns 16 cols) ----
    // B frag (k16 x n8, col): b0 = (k=2tig,2tig+1, n=g), b1 = (k=2tig+8,+9, n=g)
    uint32_t bh[2][8][2], bl[2][8][2];
#pragma unroll
    for (int nb = 0; nb < 2; nb++) {
        const int n_ = w * 16 + nb * 8 + g;
#pragma unroll
        for (int ks = 0; ks < 8; ks++) {
            const int k0 = ks * 16 + 2 * tig;
            float w00 = W1[(k0    ) * DIM + n_];
            float w01 = W1[(k0 + 1) * DIM + n_];
            float w10 = W1[(k0 + 8) * DIM + n_];
            float w11 = W1[(k0 + 9) * DIM + n_];
            float h00 = __bfloat162float(__float2bfloat16(w00));
            float h01 = __bfloat162float(__float2bfloat16(w01));
            float h10 = __bfloat162float(__float2bfloat16(w10));
            float h11 = __bfloat162float(__float2bfloat16(w11));
            bh[nb][ks][0] = pack_bf16(h00, h01);
            bh[nb][ks][1] = pack_bf16(h10, h11);
            bl[nb][ks][0] = pack_bf16(w00 - h00, w01 - h01);
            bl[nb][ks][1] = pack_bf16(w10 - h10, w11 - h11);
        }
    }

    // per-thread epilogue constants for its 4 output cols
    const int c0 = w * 16 + 2 * tig;        // nb0 cols c0, c0+1
    const int c2 = c0 + 8;                  // nb1 cols c2, c2+1
    const float b1c0 = b1[c0], b1c1 = b1[c0 + 1], b1c2 = b1[c2], b1c3 = b1[c2 + 1];
    const float w2c0 = W2[c0], w2c1 = W2[c0 + 1], w2c2 = W2[c2], w2c3 = W2[c2 + 1];
    const float b2v = b2[0];

    // ldmatrix lane addressing: row = mb*16 + (lane&15), chunk = 2*ks + (lane>>4)
    const int rl = lane & 15;
    const int hl = lane >> 4;
    const int swz = rl & 7;

    for (long long tile = blockIdx.x; tile < ntiles; tile += gridDim.x) {
        const long long row0 = tile * 128;

        __syncthreads();   // previous tile fully consumed (A smem + part)

        // ---- stage x tile -> smem bf16 hi/lo, swizzled ----
        const float4* x4g = (const float4*)x;
#pragma unroll
        for (int s = 0; s < 8; s++) {
            int cl = s * 256 + tid;            // chunk-linear 0..2047
            int r = cl >> 4, c = cl & 15;      // row, 16B-chunk (8 bf16)
            long long grow = row0 + r;
            float4 v0 = make_float4(0.f, 0.f, 0.f, 0.f), v1 = v0;
            if (grow < nrows) {
                v0 = x4g[grow * 32 + c * 2];
                v1 = x4g[grow * 32 + c * 2 + 1];
            }
            float h0 = __bfloat162float(__float2bfloat16(v0.x));
            float h1 = __bfloat162float(__float2bfloat16(v0.y));
            float h2 = __bfloat162float(__float2bfloat16(v0.z));
            float h3 = __bfloat162float(__float2bfloat16(v0.w));
            float h4 = __bfloat162float(__float2bfloat16(v1.x));
            float h5 = __bfloat162float(__float2bfloat16(v1.y));
            float h6 = __bfloat162float(__float2bfloat16(v1.z));
            float h7 = __bfloat162float(__float2bfloat16(v1.w));
            uint4 uh, ul;
            uh.x = pack_bf16(h0, h1); uh.y = pack_bf16(h2, h3);
            uh.z = pack_bf16(h4, h5); uh.w = pack_bf16(h6, h7);
            ul.x = pack_bf16(v0.x - h0, v0.y - h1);
            ul.y = pack_bf16(v0.z - h2, v0.w - h3);
            ul.z = pack_bf16(v1.x - h4, v1.y - h5);
            ul.w = pack_bf16(v1.z - h6, v1.w - h7);
            uint32_t off = (uint32_t)r * 256u + (uint32_t)((c ^ (r & 7)) << 4);
            *(uint4*)(smem + SM_AHI + off) = uh;
            *(uint4*)(smem + SM_ALO + off) = ul;
        }
        __syncthreads();

        // ---- 8 m-blocks of 16 rows; warp computes its 16 cols ----
#pragma unroll 1
        for (int mb = 0; mb < 8; mb++) {
            float acc0[4] = {0.f, 0.f, 0.f, 0.f};
            float acc1[4] = {0.f, 0.f, 0.f, 0.f};
            const uint32_t rowb = smA + (uint32_t)(mb * 16 + rl) * 256u;
#pragma unroll
            for (int ks = 0; ks < 8; ks++) {
                uint32_t ah = rowb + (uint32_t)(((2 * ks + hl) ^ swz) << 4);
                uint32_t a0, a1, a2, a3, l0, l1, l2, l3;
                LDSM_X4(a0, a1, a2, a3, ah);
                LDSM_X4(l0, l1, l2, l3, ah + SM_ALO);
                MMA_BF16(acc0, a0, a1, a2, a3, bh[0][ks][0], bh[0][ks][1]);
                MMA_BF16(acc1, a0, a1, a2, a3, bh[1][ks][0], bh[1][ks][1]);
                MMA_BF16(acc0, a0, a1, a2, a3, bl[0][ks][0], bl[0][ks][1]);
                MMA_BF16(acc1, a0, a1, a2, a3, bl[1][ks][0], bl[1][ks][1]);
                MMA_BF16(acc0, l0, l1, l2, l3, bh[0][ks][0], bh[0][ks][1]);
                MMA_BF16(acc1, l0, l1, l2, l3, bh[1][ks][0], bh[1][ks][1]);
            }
            // epilogue: rows g (d0,d1) and g+8 (d2,d3), 4 cols/thread
            float plo = tanhf(acc0[0] + b1c0) * w2c0 + tanhf(acc0[1] + b1c1) * w2c1
                      + tanhf(acc1[0] + b1c2) * w2c2 + tanhf(acc1[1] + b1c3) * w2c3;
            float phi = tanhf(acc0[2] + b1c0) * w2c0 + tanhf(acc0[3] + b1c1) * w2c1
                      + tanhf(acc1[2] + b1c2) * w2c2 + tanhf(acc1[3] + b1c3) * w2c3;
            plo += __shfl_xor_sync(0xffffffffu, plo, 1);
            plo += __shfl_xor_sync(0xffffffffu, plo, 2);
            phi += __shfl_xor_sync(0xffffffffu, phi, 1);
            phi += __shfl_xor_sync(0xffffffffu, phi, 2);
            if (tig == 0) {
                part[(mb * 16 + g) * 8 + w]     = plo;
                part[(mb * 16 + 8 + g) * 8 + w] = phi;
            }
        }
        __syncthreads();

        // ---- cross-warp reduce: score[row] = sum_w part + b2 ----
        if (tid < 128) {
            long long grow = row0 + tid;
            if (grow < nrows) {
                const float4* p4 = (const float4*)&part[tid * 8];
                float4 q0 = p4[0], q1 = p4[1];
                g_s[grow] = q0.x + q0.y + q0.z + q0.w
                          + q1.x + q1.y + q1.z + q1.w + b2v;
            }
        }
    }
}

// ---------------- K3: per-segment max + sum(exp) ----------------
__global__ void k3_stats(const void* __restrict__ idx, int n) {
    __shared__ float redm[8];
    __shared__ float redz[8];
    __shared__ int   range[2];
    __shared__ float sm_m;

    const int seg  = blockIdx.x;
    const int is64 = g_is64;
    if (threadIdx.x < 2) {
        int target = seg + (int)threadIdx.x;
        int lo = 0, hi = n;
        while (lo < hi) { int mid = (lo + hi) >> 1; if (idx_at(idx, mid, is64) < target) lo = mid + 1; else hi = mid; }
        range[threadIdx.x] = lo;
    }
    __syncthreads();
    const int b = range[0], e = range[1];

    float m = __int_as_float(0xff800000u);
    for (int i = b + threadIdx.x; i < e; i += 256) m = fmaxf(m, g_s[i]);
#pragma unroll
    for (int o = 16; o > 0; o >>= 1) m = fmaxf(m, __shfl_xor_sync(0xffffffffu, m, o));
    if ((threadIdx.x & 31) == 0) redm[threadIdx.x >> 5] = m;
    __syncthreads();
    if (threadIdx.x == 0) {
        float mm = redm[0];
#pragma unroll
        for (int wv = 1; wv < 8; wv++) mm = fmaxf(mm, redm[wv]);
        if (!(mm > -3.0e38f && mm < 3.0e38f)) mm = 0.0f;
        sm_m = mm;
    }
    __syncthreads();
    const float mfin = sm_m;

    float z = 0.f;
    for (int i = b + threadIdx.x; i < e; i += 256) z += expf(g_s[i] - mfin);
#pragma unroll
    for (int o = 16; o > 0; o >>= 1) z += __shfl_xor_sync(0xffffffffu, z, o);
    if ((threadIdx.x & 31) == 0) redz[threadIdx.x >> 5] = z;
    __syncthreads();
    if (threadIdx.x == 0) {
        float zz = 0.f;
#pragma unroll
        for (int wv = 0; wv < 8; wv++) zz += redz[wv];
        g_m[seg] = mfin; g_z[seg] = zz; g_beg[seg] = b; g_end[seg] = e;
    }
}

// ---------------- K4: alpha + weighted aggregation (warp-per-row float4) ----
__global__ void __launch_bounds__(128) k4_agg(const float* __restrict__ x,
                                              float* __restrict__ out,
                                              float* __restrict__ alpha, int n) {
    __shared__ float4 red[128];
    const int seg = blockIdx.x;
    const int b = g_beg[seg], e = g_end[seg];
    const float m    = g_m[seg];
    const float invz = 1.0f / (g_z[seg] + 1e-16f);
    const int lane = threadIdx.x & 31;
    const int r    = threadIdx.x >> 5;

    float4 acc = make_float4(0.f, 0.f, 0.f, 0.f);
    const float4* x4 = (const float4*)x;

    int i = b + r;
    for (; i + 4 < e; i += 8) {
        float s0 = g_s[i], s1 = g_s[i + 4];
        float4 v0 = x4[(long long)i * 32 + lane];
        float4 v1 = x4[(long long)(i + 4) * 32 + lane];
        float a0 = expf(s0 - m) * invz;
        float a1 = expf(s1 - m) * invz;
        acc.x = fmaf(v0.x, a0, acc.x); acc.y = fmaf(v0.y, a0, acc.y);
        acc.z = fmaf(v0.z, a0, acc.z); acc.w = fmaf(v0.w, a0, acc.w);
        acc.x = fmaf(v1.x, a1, acc.x); acc.y = fmaf(v1.y, a1, acc.y);
        acc.z = fmaf(v1.z, a1, acc.z); acc.w = fmaf(v1.w, a1, acc.w);
        if (alpha && lane == 0) { alpha[i] = a0; alpha[i + 4] = a1; }
    }
    for (; i < e; i += 4) {
        float a0 = expf(g_s[i] - m) * invz;
        float4 v0 = x4[(long long)i * 32 + lane];
        acc.x = fmaf(v0.x, a0, acc.x); acc.y = fmaf(v0.y, a0, acc.y);
        acc.z = fmaf(v0.z, a0, acc.z); acc.w = fmaf(v0.w, a0, acc.w);
        if (alpha && lane == 0) alpha[i] = a0;
    }

    red[threadIdx.x] = acc;
    __syncthreads();
    if (r == 0 && out) {
        float4 s0 = red[lane], s1 = red[lane + 32], s2 = red[lane + 64], s3 = red[lane + 96];
        float4 t;
        t.x = s0.x + s1.x + s2.x + s3.x;
        t.y = s0.y + s1.y + s2.y + s3.y;
        t.z = s0.z + s1.z + s2.z + s3.z;
        t.w = s0.w + s1.w + s2.w + s3.w;
        ((float4*)out)[seg * 32 + lane] = t;
    }
}

// ---------------- launch ----------------
extern "C" void kernel_launch(void* const* d_in, const int* in_sizes, int n_in,
                              void* d_out, int out_size) {
    const float* x   = (const float*)d_in[0];
    const float* W1  = (const float*)d_in[1];
    const float* b1  = (const float*)d_in[2];
    const float* W2  = (const float*)d_in[3];
    const float* b2  = (const float*)d_in[4];
    const void*  idx = d_in[5];
    const int n = in_sizes[0] / DIM;

    float* out_ptr = nullptr;
    float* alpha_ptr = nullptr;
    if (out_size == NSEG * DIM + n)      { out_ptr = (float*)d_out; alpha_ptr = out_ptr + NSEG * DIM; }
    else if (out_size == n)              { alpha_ptr = (float*)d_out; }
    else                                 { out_ptr = (float*)d_out;
                                           if (out_size > NSEG * DIM) alpha_ptr = out_ptr + NSEG * DIM; }

    static int smem_set = 0;
    if (!smem_set) {
        cudaFuncSetAttribute(k1_scores, cudaFuncAttributeMaxDynamicSharedMemorySize, SM_K1_SZ);
        smem_set = 1;
    }

    k0_detect<<<1, 1>>>(idx, n);

    const int ntiles = (n + 127) / 128;
    const int grid = ntiles < 296 ? ntiles : 296;
    k1_scores<<<grid, 256, SM_K1_SZ>>>(x, W1, b1, W2, b2, n, ntiles);

    k3_stats<<<NSEG, 256>>>(idx, n);
    k4_agg<<<NSEG, DIM>>>(x, out_ptr, alpha_ptr, n);
}

// round 5
// speedup vs baseline: 2.6402x; 1.1652x over previous
#include <cuda_runtime.h>
#include <cuda_bf16.h>
#include <math.h>
#include <stdint.h>

#define DIM   128
#define NSEG  4096
#define MAXN  2000128

// ---------------- scratch ----------------
__device__ float g_s[MAXN];
__device__ float g_m[NSEG];
__device__ float g_z[NSEG];
__device__ int   g_beg[NSEG];
__device__ int   g_end[NSEG];
__device__ int   g_is64;

__device__ __forceinline__ uint32_t smem_to_u32(const void* p) {
    uint32_t a;
    asm("{ .reg .u64 t; cvta.to.shared.u64 t, %1; cvt.u32.u64 %0, t; }" : "=r"(a) : "l"(p));
    return a;
}
__device__ __forceinline__ uint32_t pack_bf16(float a, float b) {
    __nv_bfloat162 t;
    t.x = __float2bfloat16(a); t.y = __float2bfloat16(b);
    return *reinterpret_cast<uint32_t*>(&t);
}
__device__ __forceinline__ float tanh_fast(float v) {
    float r;
    asm("tanh.approx.f32 %0, %1;" : "=f"(r) : "f"(v));
    return r;
}
__device__ __forceinline__ int idx_at(const void* p, int i, int is64) {
    if (is64) return (int)((const long long*)p)[i];
    return ((const int*)p)[i];
}

#define LDSM_X4(a0, a1, a2, a3, addr)                                          \
    asm volatile("ldmatrix.sync.aligned.m8n8.x4.shared.b16 {%0,%1,%2,%3},[%4];"\
        : "=r"(a0), "=r"(a1), "=r"(a2), "=r"(a3) : "r"(addr))

#define MMA_BF16(d, a0, a1, a2, a3, b0, b1)                                    \
    asm volatile("mma.sync.aligned.m16n8k16.row.col.f32.bf16.bf16.f32 "        \
        "{%0,%1,%2,%3},{%4,%5,%6,%7},{%8,%9},{%0,%1,%2,%3};"                   \
        : "+f"((d)[0]), "+f"((d)[1]), "+f"((d)[2]), "+f"((d)[3])               \
        : "r"(a0), "r"(a1), "r"(a2), "r"(a3), "r"(b0), "r"(b1))

// ---------------- K0: detect batch_idx width ----------------
__global__ void k0_detect(const void* __restrict__ idx, int n) {
    const long long* p = (const long long*)idx;
    long long j = n / 4;
    int ok = 1;
    for (int t = 0; t < 3; t++) {
        long long v = p[j + t];
        if (v < 0 || v >= NSEG) ok = 0;
    }
    g_is64 = ok;
}

// ---------------- K1: HMMA bf16x3 GEMM + tanh + dot(W2) ----------------
// smem: A_hi [0,32K), A_lo [32K,64K)  (128 rows x 128 bf16, 256B row stride,
//       16B chunks swizzled: chunk' = chunk ^ (row&7));  part [64K, 64K+4K).
#define SM_AHI  0
#define SM_ALO  32768
#define SM_PART 65536
#define SM_K1_SZ (SM_PART + 128 * 8 * 4)

__global__ void __launch_bounds__(256, 2) k1_scores(
        const float* __restrict__ x,  const float* __restrict__ W1,
        const float* __restrict__ b1, const float* __restrict__ W2,
        const float* __restrict__ b2, int nrows, int ntiles) {
    extern __shared__ char smem[];
    float* part = (float*)(smem + SM_PART);
    const uint32_t smA = smem_to_u32(smem);

    const int tid  = threadIdx.x;       // 256 threads, 8 warps
    const int w    = tid >> 5;
    const int lane = tid & 31;
    const int g    = lane >> 2;         // groupID
    const int tig  = lane & 3;          // thread-in-group

    // ---- W1^T hi/lo B-fragments, register-resident (warp owns 16 cols) ----
    uint32_t bh[2][8][2], bl[2][8][2];
#pragma unroll
    for (int nb = 0; nb < 2; nb++) {
        const int n_ = w * 16 + nb * 8 + g;
#pragma unroll
        for (int ks = 0; ks < 8; ks++) {
            const int k0 = ks * 16 + 2 * tig;
            float w00 = W1[(k0    ) * DIM + n_];
            float w01 = W1[(k0 + 1) * DIM + n_];
            float w10 = W1[(k0 + 8) * DIM + n_];
            float w11 = W1[(k0 + 9) * DIM + n_];
            float h00 = __bfloat162float(__float2bfloat16(w00));
            float h01 = __bfloat162float(__float2bfloat16(w01));
            float h10 = __bfloat162float(__float2bfloat16(w10));
            float h11 = __bfloat162float(__float2bfloat16(w11));
            bh[nb][ks][0] = pack_bf16(h00, h01);
            bh[nb][ks][1] = pack_bf16(h10, h11);
            bl[nb][ks][0] = pack_bf16(w00 - h00, w01 - h01);
            bl[nb][ks][1] = pack_bf16(w10 - h10, w11 - h11);
        }
    }

    const int c0 = w * 16 + 2 * tig;
    const int c2 = c0 + 8;
    const float b1c0 = b1[c0], b1c1 = b1[c0 + 1], b1c2 = b1[c2], b1c3 = b1[c2 + 1];
    const float w2c0 = W2[c0], w2c1 = W2[c0 + 1], w2c2 = W2[c2], w2c3 = W2[c2 + 1];
    const float b2v = b2[0];

    const int rl = lane & 15;
    const int hl = lane >> 4;
    const int swz = rl & 7;

    for (long long tile = blockIdx.x; tile < ntiles; tile += gridDim.x) {
        const long long row0 = tile * 128;

        __syncthreads();   // previous tile fully consumed

        // ---- stage x -> smem bf16 hi/lo (truncation split, PRMT pack) ----
        const float4* x4g = (const float4*)x;
#pragma unroll
        for (int s = 0; s < 8; s++) {
            int cl = s * 256 + tid;            // chunk-linear 0..2047
            int r = cl >> 4, c = cl & 15;
            long long grow = row0 + r;
            float4 v0 = make_float4(0.f, 0.f, 0.f, 0.f), v1 = v0;
            if (grow < nrows) {
                v0 = x4g[grow * 32 + c * 2];
                v1 = x4g[grow * 32 + c * 2 + 1];
            }
            uint32_t u0 = __float_as_uint(v0.x), u1 = __float_as_uint(v0.y);
            uint32_t u2 = __float_as_uint(v0.z), u3 = __float_as_uint(v0.w);
            uint32_t u4 = __float_as_uint(v1.x), u5 = __float_as_uint(v1.y);
            uint32_t u6 = __float_as_uint(v1.z), u7 = __float_as_uint(v1.w);
            uint4 uh, ul;
            uh.x = __byte_perm(u0, u1, 0x7632);    // [bf16_trunc(v0.x), bf16_trunc(v0.y)]
            uh.y = __byte_perm(u2, u3, 0x7632);
            uh.z = __byte_perm(u4, u5, 0x7632);
            uh.w = __byte_perm(u6, u7, 0x7632);
            // lo = x - float(hi_trunc), exact; round lo pair to bf16x2
            ul.x = pack_bf16(v0.x - __uint_as_float(u0 & 0xffff0000u),
                             v0.y - __uint_as_float(u1 & 0xffff0000u));
            ul.y = pack_bf16(v0.z - __uint_as_float(u2 & 0xffff0000u),
                             v0.w - __uint_as_float(u3 & 0xffff0000u));
            ul.z = pack_bf16(v1.x - __uint_as_float(u4 & 0xffff0000u),
                             v1.y - __uint_as_float(u5 & 0xffff0000u));
            ul.w = pack_bf16(v1.z - __uint_as_float(u6 & 0xffff0000u),
                             v1.w - __uint_as_float(u7 & 0xffff0000u));
            uint32_t off = (uint32_t)r * 256u + (uint32_t)((c ^ (r & 7)) << 4);
            *(uint4*)(smem + SM_AHI + off) = uh;
            *(uint4*)(smem + SM_ALO + off) = ul;
        }
        __syncthreads();

        // ---- 8 m-blocks of 16 rows ----
#pragma unroll 1
        for (int mb = 0; mb < 8; mb++) {
            float acc0[4] = {0.f, 0.f, 0.f, 0.f};
            float acc1[4] = {0.f, 0.f, 0.f, 0.f};
            const uint32_t rowb = smA + (uint32_t)(mb * 16 + rl) * 256u;
#pragma unroll
            for (int ks = 0; ks < 8; ks++) {
                uint32_t ah = rowb + (uint32_t)(((2 * ks + hl) ^ swz) << 4);
                uint32_t a0, a1, a2, a3, l0, l1, l2, l3;
                LDSM_X4(a0, a1, a2, a3, ah);
                LDSM_X4(l0, l1, l2, l3, ah + SM_ALO);
                MMA_BF16(acc0, a0, a1, a2, a3, bh[0][ks][0], bh[0][ks][1]);
                MMA_BF16(acc1, a0, a1, a2, a3, bh[1][ks][0], bh[1][ks][1]);
                MMA_BF16(acc0, a0, a1, a2, a3, bl[0][ks][0], bl[0][ks][1]);
                MMA_BF16(acc1, a0, a1, a2, a3, bl[1][ks][0], bl[1][ks][1]);
                MMA_BF16(acc0, l0, l1, l2, l3, bh[0][ks][0], bh[0][ks][1]);
                MMA_BF16(acc1, l0, l1, l2, l3, bh[1][ks][0], bh[1][ks][1]);
            }
            float plo = tanh_fast(acc0[0] + b1c0) * w2c0 + tanh_fast(acc0[1] + b1c1) * w2c1
                      + tanh_fast(acc1[0] + b1c2) * w2c2 + tanh_fast(acc1[1] + b1c3) * w2c3;
            float phi = tanh_fast(acc0[2] + b1c0) * w2c0 + tanh_fast(acc0[3] + b1c1) * w2c1
                      + tanh_fast(acc1[2] + b1c2) * w2c2 + tanh_fast(acc1[3] + b1c3) * w2c3;
            plo += __shfl_xor_sync(0xffffffffu, plo, 1);
            plo += __shfl_xor_sync(0xffffffffu, plo, 2);
            phi += __shfl_xor_sync(0xffffffffu, phi, 1);
            phi += __shfl_xor_sync(0xffffffffu, phi, 2);
            if (tig == 0) {
                part[(mb * 16 + g) * 8 + w]     = plo;
                part[(mb * 16 + 8 + g) * 8 + w] = phi;
            }
        }
        __syncthreads();

        // ---- cross-warp reduce ----
        if (tid < 128) {
            long long grow = row0 + tid;
            if (grow < nrows) {
                const float4* p4 = (const float4*)&part[tid * 8];
                float4 q0 = p4[0], q1 = p4[1];
                g_s[grow] = q0.x + q0.y + q0.z + q0.w
                          + q1.x + q1.y + q1.z + q1.w + b2v;
            }
        }
    }
}

// ---------------- K3: per-segment max + sum(exp) ----------------
__global__ void k3_stats(const void* __restrict__ idx, int n) {
    __shared__ float redm[8];
    __shared__ float redz[8];
    __shared__ int   range[2];
    __shared__ float sm_m;

    const int seg  = blockIdx.x;
    const int is64 = g_is64;
    if (threadIdx.x < 2) {
        int target = seg + (int)threadIdx.x;
        int lo = 0, hi = n;
        while (lo < hi) { int mid = (lo + hi) >> 1; if (idx_at(idx, mid, is64) < target) lo = mid + 1; else hi = mid; }
        range[threadIdx.x] = lo;
    }
    __syncthreads();
    const int b = range[0], e = range[1];

    float m = __int_as_float(0xff800000u);
    for (int i = b + threadIdx.x; i < e; i += 256) m = fmaxf(m, g_s[i]);
#pragma unroll
    for (int o = 16; o > 0; o >>= 1) m = fmaxf(m, __shfl_xor_sync(0xffffffffu, m, o));
    if ((threadIdx.x & 31) == 0) redm[threadIdx.x >> 5] = m;
    __syncthreads();
    if (threadIdx.x == 0) {
        float mm = redm[0];
#pragma unroll
        for (int wv = 1; wv < 8; wv++) mm = fmaxf(mm, redm[wv]);
        if (!(mm > -3.0e38f && mm < 3.0e38f)) mm = 0.0f;
        sm_m = mm;
    }
    __syncthreads();
    const float mfin = sm_m;

    float z = 0.f;
    for (int i = b + threadIdx.x; i < e; i += 256) z += expf(g_s[i] - mfin);
#pragma unroll
    for (int o = 16; o > 0; o >>= 1) z += __shfl_xor_sync(0xffffffffu, z, o);
    if ((threadIdx.x & 31) == 0) redz[threadIdx.x >> 5] = z;
    __syncthreads();
    if (threadIdx.x == 0) {
        float zz = 0.f;
#pragma unroll
        for (int wv = 0; wv < 8; wv++) zz += redz[wv];
        g_m[seg] = mfin; g_z[seg] = zz; g_beg[seg] = b; g_end[seg] = e;
    }
}

// ---------------- K4: alpha + weighted aggregation (8 warps/row-strided) ----
__global__ void __launch_bounds__(256) k4_agg(const float* __restrict__ x,
                                              float* __restrict__ out,
                                              float* __restrict__ alpha, int n) {
    __shared__ float4 red[256];
    const int seg = blockIdx.x;
    const int b = g_beg[seg], e = g_end[seg];
    const float m    = g_m[seg];
    const float invz = 1.0f / (g_z[seg] + 1e-16f);
    const int lane = threadIdx.x & 31;
    const int r    = threadIdx.x >> 5;       // 8 warps, rows strided by 8

    float4 acc = make_float4(0.f, 0.f, 0.f, 0.f);
    const float4* x4 = (const float4*)x;

    int i = b + r;
    for (; i + 8 < e; i += 16) {
        float s0 = g_s[i], s1 = g_s[i + 8];
        float4 v0 = x4[(long long)i * 32 + lane];
        float4 v1 = x4[(long long)(i + 8) * 32 + lane];
        float a0 = expf(s0 - m) * invz;
        float a1 = expf(s1 - m) * invz;
        acc.x = fmaf(v0.x, a0, acc.x); acc.y = fmaf(v0.y, a0, acc.y);
        acc.z = fmaf(v0.z, a0, acc.z); acc.w = fmaf(v0.w, a0, acc.w);
        acc.x = fmaf(v1.x, a1, acc.x); acc.y = fmaf(v1.y, a1, acc.y);
        acc.z = fmaf(v1.z, a1, acc.z); acc.w = fmaf(v1.w, a1, acc.w);
        if (alpha && lane == 0) { alpha[i] = a0; alpha[i + 8] = a1; }
    }
    for (; i < e; i += 8) {
        float a0 = expf(g_s[i] - m) * invz;
        float4 v0 = x4[(long long)i * 32 + lane];
        acc.x = fmaf(v0.x, a0, acc.x); acc.y = fmaf(v0.y, a0, acc.y);
        acc.z = fmaf(v0.z, a0, acc.z); acc.w = fmaf(v0.w, a0, acc.w);
        if (alpha && lane == 0) alpha[i] = a0;
    }

    red[threadIdx.x] = acc;
    __syncthreads();
    if (r == 0 && out) {
        float4 t = make_float4(0.f, 0.f, 0.f, 0.f);
#pragma unroll
        for (int k = 0; k < 8; k++) {
            float4 s = red[lane + 32 * k];
            t.x += s.x; t.y += s.y; t.z += s.z; t.w += s.w;
        }
        ((float4*)out)[seg * 32 + lane] = t;
    }
}

// ---------------- launch ----------------
extern "C" void kernel_launch(void* const* d_in, const int* in_sizes, int n_in,
                              void* d_out, int out_size) {
    const float* x   = (const float*)d_in[0];
    const float* W1  = (const float*)d_in[1];
    const float* b1  = (const float*)d_in[2];
    const float* W2  = (const float*)d_in[3];
    const float* b2  = (const float*)d_in[4];
    const void*  idx = d_in[5];
    const int n = in_sizes[0] / DIM;

    float* out_ptr = nullptr;
    float* alpha_ptr = nullptr;
    if (out_size == NSEG * DIM + n)      { out_ptr = (float*)d_out; alpha_ptr = out_ptr + NSEG * DIM; }
    else if (out_size == n)              { alpha_ptr = (float*)d_out; }
    else                                 { out_ptr = (float*)d_out;
                                           if (out_size > NSEG * DIM) alpha_ptr = out_ptr + NSEG * DIM; }

    static int smem_set = 0;
    if (!smem_set) {
        cudaFuncSetAttribute(k1_scores, cudaFuncAttributeMaxDynamicSharedMemorySize, SM_K1_SZ);
        smem_set = 1;
    }

    k0_detect<<<1, 1>>>(idx, n);

    const int ntiles = (n + 127) / 128;
    const int grid = ntiles < 296 ? ntiles : 296;
    k1_scores<<<grid, 256, SM_K1_SZ>>>(x, W1, b1, W2, b2, n, ntiles);

    k3_stats<<<NSEG, 256>>>(idx, n);
    k4_agg<<<NSEG, 256>>>(x, out_ptr, alpha_ptr, n);
}

// round 10
// speedup vs baseline: 2.6797x; 1.0149x over previous
#include <cuda_runtime.h>
#include <cuda_bf16.h>
#include <math.h>
#include <stdint.h>

#define DIM   128
#define NSEG  4096
#define MAXN  2000128

// ---------------- scratch ----------------
__device__ float g_s[MAXN];
__device__ float g_m[NSEG];
__device__ float g_z[NSEG];
__device__ int   g_beg[NSEG];
__device__ int   g_end[NSEG];
__device__ int   g_is64;

__device__ __forceinline__ uint32_t smem_to_u32(const void* p) {
    uint32_t a;
    asm("{ .reg .u64 t; cvta.to.shared.u64 t, %1; cvt.u32.u64 %0, t; }" : "=r"(a) : "l"(p));
    return a;
}
__device__ __forceinline__ uint32_t pack_bf16(float a, float b) {
    __nv_bfloat162 t;
    t.x = __float2bfloat16(a); t.y = __float2bfloat16(b);
    return *reinterpret_cast<uint32_t*>(&t);
}
__device__ __forceinline__ float tanh_fast(float v) {
    float r;
    asm("tanh.approx.f32 %0, %1;" : "=f"(r) : "f"(v));
    return r;
}
__device__ __forceinline__ float4 ldcs4(const float4* p) {
    float4 v;
    asm volatile("ld.global.cs.v4.f32 {%0,%1,%2,%3}, [%4];"
                 : "=f"(v.x), "=f"(v.y), "=f"(v.z), "=f"(v.w) : "l"(p));
    return v;
}
__device__ __forceinline__ int idx_at(const void* p, int i, int is64) {
    if (is64) return (int)((const long long*)p)[i];
    return ((const int*)p)[i];
}

#define LDSM_X4(a0, a1, a2, a3, addr)                                          \
    asm volatile("ldmatrix.sync.aligned.m8n8.x4.shared.b16 {%0,%1,%2,%3},[%4];"\
        : "=r"(a0), "=r"(a1), "=r"(a2), "=r"(a3) : "r"(addr))

#define MMA_BF16(d, a0, a1, a2, a3, b0, b1)                                    \
    asm volatile("mma.sync.aligned.m16n8k16.row.col.f32.bf16.bf16.f32 "        \
        "{%0,%1,%2,%3},{%4,%5,%6,%7},{%8,%9},{%0,%1,%2,%3};"                   \
        : "+f"((d)[0]), "+f"((d)[1]), "+f"((d)[2]), "+f"((d)[3])               \
        : "r"(a0), "r"(a1), "r"(a2), "r"(a3), "r"(b0), "r"(b1))

// ---------------- K0: detect batch_idx width ----------------
__global__ void k0_detect(const void* __restrict__ idx, int n) {
    const long long* p = (const long long*)idx;
    long long j = n / 4;
    int ok = 1;
    for (int t = 0; t < 3; t++) {
        long long v = p[j + t];
        if (v < 0 || v >= NSEG) ok = 0;
    }
    g_is64 = ok;
}

// ---------------- K1: HMMA bf16x3 GEMM + tanh + dot(W2) ----------------
// 128 threads (4 warps), tile = 64 rows. Each warp owns 32 output columns
// (4 n-blocks); A fragments are read once per warp and feed 12 MMAs.
// smem: A_hi [0,16K), A_lo [16K,32K)  (64 rows x 128 bf16, 256B row stride,
//       16B chunks swizzled: chunk' = chunk ^ (row&7)); part [32K, 32K+1K).
#define SM_AHI  0
#define SM_ALO  16384
#define SM_PART 32768
#define SM_K1_SZ (SM_PART + 64 * 4 * 4)

__global__ void __launch_bounds__(128, 2) k1_scores(
        const float* __restrict__ x,  const float* __restrict__ W1,
        const float* __restrict__ b1, const float* __restrict__ W2,
        const float* __restrict__ b2, int nrows, int ntiles) {
    extern __shared__ char smem[];
    float* part = (float*)(smem + SM_PART);
    const uint32_t smA = smem_to_u32(smem);

    const int tid  = threadIdx.x;       // 128 threads, 4 warps
    const int w    = tid >> 5;
    const int lane = tid & 31;
    const int g    = lane >> 2;         // groupID (row in fragment)
    const int tig  = lane & 3;          // thread-in-group (col pair)

    // ---- W1^T hi/lo B-fragments, register-resident (warp owns 32 cols) ----
    uint32_t bh[4][8][2], bl[4][8][2];
#pragma unroll
    for (int nb = 0; nb < 4; nb++) {
        const int n_ = w * 32 + nb * 8 + g;
#pragma unroll
        for (int ks = 0; ks < 8; ks++) {
            const int k0 = ks * 16 + 2 * tig;
            float w00 = W1[(k0    ) * DIM + n_];
            float w01 = W1[(k0 + 1) * DIM + n_];
            float w10 = W1[(k0 + 8) * DIM + n_];
            float w11 = W1[(k0 + 9) * DIM + n_];
            float h00 = __bfloat162float(__float2bfloat16(w00));
            float h01 = __bfloat162float(__float2bfloat16(w01));
            float h10 = __bfloat162float(__float2bfloat16(w10));
            float h11 = __bfloat162float(__float2bfloat16(w11));
            bh[nb][ks][0] = pack_bf16(h00, h01);
            bh[nb][ks][1] = pack_bf16(h10, h11);
            bl[nb][ks][0] = pack_bf16(w00 - h00, w01 - h01);
            bl[nb][ks][1] = pack_bf16(w10 - h10, w11 - h11);
        }
    }

    // epilogue coeffs: cols w*32 + nb*8 + 2tig (+1), nb = 0..3
    float b1c[8], w2c[8];
#pragma unroll
    for (int nb = 0; nb < 4; nb++) {
        int c = w * 32 + nb * 8 + 2 * tig;
        b1c[2 * nb]     = b1[c];     b1c[2 * nb + 1] = b1[c + 1];
        w2c[2 * nb]     = W2[c];     w2c[2 * nb + 1] = W2[c + 1];
    }
    const float b2v = b2[0];

    const int rl = lane & 15;
    const int hl = lane >> 4;
    const int swz = rl & 7;

    for (long long tile = blockIdx.x; tile < ntiles; tile += gridDim.x) {
        const long long row0 = tile * 64;

        __syncthreads();   // previous tile fully consumed

        // ---- stage x -> smem bf16 hi/lo (truncation split, PRMT pack) ----
        const float4* x4g = (const float4*)x;
#pragma unroll
        for (int s = 0; s < 8; s++) {
            int cl = s * 128 + tid;            // chunk-linear 0..1023
            int r = cl >> 4, c = cl & 15;      // row (0..63), 16B-chunk
            long long grow = row0 + r;
            float4 v0 = make_float4(0.f, 0.f, 0.f, 0.f), v1 = v0;
            if (grow < nrows) {
                v0 = ldcs4(&x4g[grow * 32 + c * 2]);
                v1 = ldcs4(&x4g[grow * 32 + c * 2 + 1]);
            }
            uint32_t u0 = __float_as_uint(v0.x), u1 = __float_as_uint(v0.y);
            uint32_t u2 = __float_as_uint(v0.z), u3 = __float_as_uint(v0.w);
            uint32_t u4 = __float_as_uint(v1.x), u5 = __float_as_uint(v1.y);
            uint32_t u6 = __float_as_uint(v1.z), u7 = __float_as_uint(v1.w);
            uint4 uh, ul;
            uh.x = __byte_perm(u0, u1, 0x7632);
            uh.y = __byte_perm(u2, u3, 0x7632);
            uh.z = __byte_perm(u4, u5, 0x7632);
            uh.w = __byte_perm(u6, u7, 0x7632);
            ul.x = pack_bf16(v0.x - __uint_as_float(u0 & 0xffff0000u),
                             v0.y - __uint_as_float(u1 & 0xffff0000u));
            ul.y = pack_bf16(v0.z - __uint_as_float(u2 & 0xffff0000u),
                             v0.w - __uint_as_float(u3 & 0xffff0000u));
            ul.z = pack_bf16(v1.x - __uint_as_float(u4 & 0xffff0000u),
                             v1.y - __uint_as_float(u5 & 0xffff0000u));
            ul.w = pack_bf16(v1.z - __uint_as_float(u6 & 0xffff0000u),
                             v1.w - __uint_as_float(u7 & 0xffff0000u));
            uint32_t off = (uint32_t)r * 256u + (uint32_t)((c ^ (r & 7)) << 4);
            *(uint4*)(smem + SM_AHI + off) = uh;
            *(uint4*)(smem + SM_ALO + off) = ul;
        }
        __syncthreads();

        // ---- 4 m-blocks of 16 rows; each warp computes its 32 cols ----
#pragma unroll 1
        for (int mb = 0; mb < 4; mb++) {
            float acc[4][4];
#pragma unroll
            for (int nb = 0; nb < 4; nb++)
#pragma unroll
                for (int q = 0; q < 4; q++) acc[nb][q] = 0.f;
            const uint32_t rowb = smA + (uint32_t)(mb * 16 + rl) * 256u;
#pragma unroll
            for (int ks = 0; ks < 8; ks++) {
                uint32_t ah = rowb + (uint32_t)(((2 * ks + hl) ^ swz) << 4);
                uint32_t a0, a1, a2, a3, l0, l1, l2, l3;
                LDSM_X4(a0, a1, a2, a3, ah);
                LDSM_X4(l0, l1, l2, l3, ah + SM_ALO);
#pragma unroll
                for (int nb = 0; nb < 4; nb++)
                    MMA_BF16(acc[nb], a0, a1, a2, a3, bh[nb][ks][0], bh[nb][ks][1]);
#pragma unroll
                for (int nb = 0; nb < 4; nb++)
                    MMA_BF16(acc[nb], a0, a1, a2, a3, bl[nb][ks][0], bl[nb][ks][1]);
#pragma unroll
                for (int nb = 0; nb < 4; nb++)
                    MMA_BF16(acc[nb], l0, l1, l2, l3, bh[nb][ks][0], bh[nb][ks][1]);
            }
            float plo = 0.f, phi = 0.f;
#pragma unroll
            for (int nb = 0; nb < 4; nb++) {
                plo += tanh_fast(acc[nb][0] + b1c[2 * nb])     * w2c[2 * nb]
                     + tanh_fast(acc[nb][1] + b1c[2 * nb + 1]) * w2c[2 * nb + 1];
                phi += tanh_fast(acc[nb][2] + b1c[2 * nb])     * w2c[2 * nb]
                     + tanh_fast(acc[nb][3] + b1c[2 * nb + 1]) * w2c[2 * nb + 1];
            }
            plo += __shfl_xor_sync(0xffffffffu, plo, 1);
            plo += __shfl_xor_sync(0xffffffffu, plo, 2);
            phi += __shfl_xor_sync(0xffffffffu, phi, 1);
            phi += __shfl_xor_sync(0xffffffffu, phi, 2);
            if (tig == 0) {
                part[(mb * 16 + g) * 4 + w]     = plo;
                part[(mb * 16 + 8 + g) * 4 + w] = phi;
            }
        }
        __syncthreads();

        // ---- cross-warp reduce: score = sum over 4 warps + b2 ----
        if (tid < 64) {
            long long grow = row0 + tid;
            if (grow < nrows) {
                float4 q = ((const float4*)part)[tid];
                g_s[grow] = q.x + q.y + q.z + q.w + b2v;
            }
        }
    }
}

// ---------------- K3: per-segment max + sum(exp) ----------------
__global__ void k3_stats(const void* __restrict__ idx, int n) {
    __shared__ float redm[8];
    __shared__ float redz[8];
    __shared__ int   range[2];
    __shared__ float sm_m;

    const int seg  = blockIdx.x;
    const int is64 = g_is64;
    if (threadIdx.x < 2) {
        int target = seg + (int)threadIdx.x;
        int lo = 0, hi = n;
        while (lo < hi) { int mid = (lo + hi) >> 1; if (idx_at(idx, mid, is64) < target) lo = mid + 1; else hi = mid; }
        range[threadIdx.x] = lo;
    }
    __syncthreads();
    const int b = range[0], e = range[1];

    float m = __int_as_float(0xff800000u);
    for (int i = b + threadIdx.x; i < e; i += 256) m = fmaxf(m, g_s[i]);
#pragma unroll
    for (int o = 16; o > 0; o >>= 1) m = fmaxf(m, __shfl_xor_sync(0xffffffffu, m, o));
    if ((threadIdx.x & 31) == 0) redm[threadIdx.x >> 5] = m;
    __syncthreads();
    if (threadIdx.x == 0) {
        float mm = redm[0];
#pragma unroll
        for (int wv = 1; wv < 8; wv++) mm = fmaxf(mm, redm[wv]);
        if (!(mm > -3.0e38f && mm < 3.0e38f)) mm = 0.0f;
        sm_m = mm;
    }
    __syncthreads();
    const float mfin = sm_m;

    float z = 0.f;
    for (int i = b + threadIdx.x; i < e; i += 256) z += expf(g_s[i] - mfin);
#pragma unroll
    for (int o = 16; o > 0; o >>= 1) z += __shfl_xor_sync(0xffffffffu, z, o);
    if ((threadIdx.x & 31) == 0) redz[threadIdx.x >> 5] = z;
    __syncthreads();
    if (threadIdx.x == 0) {
        float zz = 0.f;
#pragma unroll
        for (int wv = 0; wv < 8; wv++) zz += redz[wv];
        g_m[seg] = mfin; g_z[seg] = zz; g_beg[seg] = b; g_end[seg] = e;
    }
}

// ---------------- K4: alpha + weighted aggregation (8 warps/row-strided) ----
__global__ void __launch_bounds__(256) k4_agg(const float* __restrict__ x,
                                              float* __restrict__ out,
                                              float* __restrict__ alpha, int n) {
    __shared__ float4 red[256];
    const int seg = blockIdx.x;
    const int b = g_beg[seg], e = g_end[seg];
    const float m    = g_m[seg];
    const float invz = 1.0f / (g_z[seg] + 1e-16f);
    const int lane = threadIdx.x & 31;
    const int r    = threadIdx.x >> 5;       // 8 warps, rows strided by 8

    float4 acc = make_float4(0.f, 0.f, 0.f, 0.f);
    const float4* x4 = (const float4*)x;

    int i = b + r;
    for (; i + 8 < e; i += 16) {
        float s0 = g_s[i], s1 = g_s[i + 8];
        float4 v0 = ldcs4(&x4[(long long)i * 32 + lane]);
        float4 v1 = ldcs4(&x4[(long long)(i + 8) * 32 + lane]);
        float a0 = expf(s0 - m) * invz;
        float a1 = expf(s1 - m) * invz;
        acc.x = fmaf(v0.x, a0, acc.x); acc.y = fmaf(v0.y, a0, acc.y);
        acc.z = fmaf(v0.z, a0, acc.z); acc.w = fmaf(v0.w, a0, acc.w);
        acc.x = fmaf(v1.x, a1, acc.x); acc.y = fmaf(v1.y, a1, acc.y);
        acc.z = fmaf(v1.z, a1, acc.z); acc.w = fmaf(v1.w, a1, acc.w);
        if (alpha && lane == 0) { alpha[i] = a0; alpha[i + 8] = a1; }
    }
    for (; i < e; i += 8) {
        float a0 = expf(g_s[i] - m) * invz;
        float4 v0 = ldcs4(&x4[(long long)i * 32 + lane]);
        acc.x = fmaf(v0.x, a0, acc.x); acc.y = fmaf(v0.y, a0, acc.y);
        acc.z = fmaf(v0.z, a0, acc.z); acc.w = fmaf(v0.w, a0, acc.w);
        if (alpha && lane == 0) alpha[i] = a0;
    }

    red[threadIdx.x] = acc;
    __syncthreads();
    if (r == 0 && out) {
        float4 t = make_float4(0.f, 0.f, 0.f, 0.f);
#pragma unroll
        for (int k = 0; k < 8; k++) {
            float4 s = red[lane + 32 * k];
            t.x += s.x; t.y += s.y; t.z += s.z; t.w += s.w;
        }
        ((float4*)out)[seg * 32 + lane] = t;
    }
}

// ---------------- launch ----------------
extern "C" void kernel_launch(void* const* d_in, const int* in_sizes, int n_in,
                              void* d_out, int out_size) {
    const float* x   = (const float*)d_in[0];
    const float* W1  = (const float*)d_in[1];
    const float* b1  = (const float*)d_in[2];
    const float* W2  = (const float*)d_in[3];
    const float* b2  = (const float*)d_in[4];
    const void*  idx = d_in[5];
    const int n = in_sizes[0] / DIM;

    float* out_ptr = nullptr;
    float* alpha_ptr = nullptr;
    if (out_size == NSEG * DIM + n)      { out_ptr = (float*)d_out; alpha_ptr = out_ptr + NSEG * DIM; }
    else if (out_size == n)              { alpha_ptr = (float*)d_out; }
    else                                 { out_ptr = (float*)d_out;
                                           if (out_size > NSEG * DIM) alpha_ptr = out_ptr + NSEG * DIM; }

    static int smem_set = 0;
    if (!smem_set) {
        cudaFuncSetAttribute(k1_scores, cudaFuncAttributeMaxDynamicSharedMemorySize, SM_K1_SZ);
        smem_set = 1;
    }

    k0_detect<<<1, 1>>>(idx, n);

    const int ntiles = (n + 63) / 64;
    const int grid = ntiles < 296 ? ntiles : 296;
    k1_scores<<<grid, 128, SM_K1_SZ>>>(x, W1, b1, W2, b2, n, ntiles);

    k3_stats<<<NSEG, 256>>>(idx, n);
    k4_agg<<<NSEG, 256>>>(x, out_ptr, alpha_ptr, n);
}